// round 13
// baseline (speedup 1.0000x reference)
#include <cuda_runtime.h>

// ---------------------------------------------------------------------------
// EquivGNNEncoder on GB300, v9 = v8 + node-blocked dense phases (R=4).
// k_gnn is LSU-bound: dense weight re-reads were 32x redundant (one full
// weight read per node). Dense phases now run on 64 threads, each weight
// LDS amortized over 4 nodes -> dense smem traffic ~2x lower.
// ---------------------------------------------------------------------------

#define MAXN (1 << 17)
#define MAXB 4096

typedef unsigned long long u64;

__device__ float g_hg[MAXB * 80];

__device__ __forceinline__ void cpa16(void* s, const void* g) {
    unsigned sa = (unsigned)__cvta_generic_to_shared(s);
    asm volatile("cp.async.cg.shared.global [%0], [%1], 16;\n" :: "r"(sa), "l"(g));
}
__device__ __forceinline__ void cpa_commit() {
    asm volatile("cp.async.commit_group;\n");
}
template<int N> __device__ __forceinline__ void cpa_wait() {
    asm volatile("cp.async.wait_group %0;\n" :: "n"(N) : "memory");
}

__device__ __forceinline__ u64 pk2(float lo, float hi) {
    u64 r; asm("mov.b64 %0, {%1, %2};" : "=l"(r) : "f"(lo), "f"(hi)); return r;
}
__device__ __forceinline__ u64 splat2(float v) { return pk2(v, v); }
__device__ __forceinline__ void upk2(u64 v, float& lo, float& hi) {
    asm("mov.b64 {%0, %1}, %2;" : "=f"(lo), "=f"(hi) : "l"(v));
}
__device__ __forceinline__ void ffma2(u64& d, u64 a, u64 b) {
    asm("fma.rn.f32x2 %0, %1, %2, %0;" : "+l"(d) : "l"(a), "l"(b));
}
__device__ __forceinline__ void fadd2(u64& d, u64 a) {
    asm("add.rn.f32x2 %0, %1, %0;" : "+l"(d) : "l"(a));
}

// smem float offsets (total 14272 floats = 57088 B -> 4 CTAs/SM):
#define SPOS 0        // pos float4 [32]        (128)
#define SS   128      // [n] stride 36          (1152)
#define SV4  1280     // float4 [n*17+w]        (2176)
#define SSB  3456     // S_bar [n] stride 36    (1152)
#define SR   4608     // r [n] stride 20        (640)
#define SVB  5248     // Vbar [(n*3+i)]*20      (1920)
#define SP   7168     // p [(n*3+i)]*36         (3456)
#define SAS  7168     // alias over sP          (1152)
#define SAV  8320     // alias over sP          (1920)
#define SW   10624    // 3584: [W1 0|W2 1024|W3 1536|W4 1792|Ws 2304|Wv 3328]
#define SADJ 14208
#define SZI  14240
#define SMEM_GNN (14272 * 4)

__global__ void __launch_bounds__(256, 4) k_gnn(
    const float* __restrict__ pos, const int* __restrict__ z,
    const float* __restrict__ emb, const float* __restrict__ Ws2n,
    const float* __restrict__ W1g, const float* __restrict__ W2g,
    const float* __restrict__ W3g, const float* __restrict__ W4g,
    const float* __restrict__ Wsg, const float* __restrict__ Wvg)
{
    extern __shared__ float sm[];
    float* sW = sm + SW;
    unsigned* sAdj = (unsigned*)(sm + SADJ);
    int*      sZi  = (int*)(sm + SZI);

    const int g    = blockIdx.x;
    const int tid  = threadIdx.x;
    const int n8   = tid >> 3;     // node for 256-thread phases
    const int q8   = tid & 7;
    const int warp = tid >> 5;
    const int lane = tid & 31;
    const int dng  = tid >> 3;     // dense phases use tid<64: dng 0..7
    const int dq   = tid & 7;

    const float SQRT3    = 1.7320508075688772f;
    const float INVS3    = 0.5773502691896258f;
    const float C_S      = 0.14433756729740643f;  // 1/sqrt(48)
    const float C_VI     = 0.14433756729740643f;
    const float INV_SQ32 = 0.17677669529663687f;
    const float R2       = 25.0f;

    // ---- stage Ws2n via cp.async; load statics ----
    cpa16((float4*)sW + tid, (const float4*)Ws2n + tid);
    cpa_commit();
    if (tid < 96) {
        int n = tid / 3, c = tid - n * 3;
        sm[SPOS + n * 4 + c] = pos[g * 96 + tid];
    }
    if (tid < 32) {
        sm[SPOS + tid * 4 + 3] = 0.f;
        sZi[tid] = z[g * 32 + tid];
    }
    __syncthreads();

    // ---- adjacency from pos (bit-identical to reference predicate) ----
    {
        const float4* pos4 = (const float4*)(sm + SPOS);
        float4 pm = pos4[lane];
        #pragma unroll
        for (int nn = 0; nn < 4; ++nn) {
            int n = warp * 4 + nn;
            float4 pn = pos4[n];
            float dx = __fsub_rn(pn.x, pm.x);
            float dy = __fsub_rn(pn.y, pm.y);
            float dz = __fsub_rn(pn.z, pm.z);
            float d2 = __fadd_rn(__fadd_rn(__fmul_rn(dx, dx), __fmul_rn(dy, dy)),
                                 __fmul_rn(dz, dz));
            unsigned msk = __ballot_sync(0xffffffffu, d2 <= R2 && d2 > 0.f);
            if (lane == 0) sAdj[n] = msk;
        }
    }

    // ---- emb gather, v = 0 ----
    {
        const float4* emb4 = (const float4*)emb;
        ((float4*)(sm + SSB + n8 * 36))[q8] = emb4[sZi[n8] * 8 + q8];
        float4 z4 = {0.f, 0.f, 0.f, 0.f};
        for (int i = tid; i < 544; i += 256) ((float4*)(sm + SV4))[i] = z4;
    }
    cpa_wait<0>();
    __syncthreads();

    // ---- initial s = (emb @ Ws2n)/sqrt(32), packed, 256 threads ----
    {
        u64 a01 = 0, a23 = 0;
        const float4* inf = (const float4*)(sm + SSB + n8 * 36);
        const ulonglong2* wf = (const ulonglong2*)sW;
        #pragma unroll
        for (int u4 = 0; u4 < 8; ++u4) {
            float4 s4 = inf[u4];
            float sv[4] = {s4.x, s4.y, s4.z, s4.w};
            #pragma unroll
            for (int j = 0; j < 4; ++j) {
                u64 sj = splat2(sv[j]);
                ulonglong2 w = wf[(u4 * 4 + j) * 8 + q8];
                ffma2(a01, sj, w.x);
                ffma2(a23, sj, w.y);
            }
        }
        float a0, a1, a2, a3;
        upk2(a01, a0, a1); upk2(a23, a2, a3);
        float4 o;
        o.x = a0 * INV_SQ32; o.y = a1 * INV_SQ32;
        o.z = a2 * INV_SQ32; o.w = a3 * INV_SQ32;
        ((float4*)(sm + SS + n8 * 36))[q8] = o;
    }
    __syncthreads();

    // ---- layers ----
    for (int l = 0; l < 3; ++l) {
        // stage layer weights directly from the 6 arrays (overlaps gather)
        {
            float4* wd = (float4*)sW;
            cpa16(wd + tid,        (const float4*)W1g + l * 256 + tid);        // W1
            cpa16(wd + 576 + tid,  (const float4*)Wsg + l * 256 + tid);        // Ws
            if (tid < 128)
                cpa16(wd + 256 + tid, (const float4*)W2g + l * 128 + tid);     // W2
            else
                cpa16(wd + 448 + (tid - 128),
                      (const float4*)W4g + l * 128 + (tid - 128));             // W4
            if (tid < 64)
                cpa16(wd + 384 + tid, (const float4*)W3g + l * 64 + tid);      // W3
            else if (tid < 128)
                cpa16(wd + 832 + (tid - 64),
                      (const float4*)Wvg + l * 64 + (tid - 64));               // Wv
            cpa_commit();
        }

        // ---- edge gather: warp per 4 nodes, packed (x,y) pairs ----
        {
            int w2 = lane & 15;
            const float4* v4p = (const float4*)(sm + SV4);
            const float4* pos4 = (const float4*)(sm + SPOS);
            for (int nn = 0; nn < 4; ++nn) {
                int n = warp * 4 + nn;
                float4 pn = pos4[n];
                unsigned am = sAdj[n];
                float aS = 0.f, aPz = 0.f, aVz = 0.f, aRz = 0.f;
                u64 aPxy = 0, aVxy = 0, aRxy = 0;
                while (am) {
                    int m = __ffs(am) - 1;
                    am &= am - 1;
                    float4 pm = pos4[m];
                    float dx = pn.x - pm.x;
                    float dy = pn.y - pm.y;
                    float dz = pn.z - pm.z;
                    float iv = SQRT3 * rsqrtf(dx * dx + dy * dy + dz * dz);
                    float sx = dx * iv, sy = dy * iv, sz = dz * iv;
                    u64 sxy = pk2(sx, sy);
                    float su = sm[SS + m * 36 + lane];
                    aS += su;
                    ffma2(aPxy, splat2(su), sxy);
                    aPz = fmaf(su, sz, aPz);
                    ulonglong2 vv = *(const ulonglong2*)(v4p + m * 17 + w2);
                    fadd2(aVxy, vv.x);            // (vx, vy)
                    float vz, vpad;
                    upk2(vv.y, vz, vpad);
                    aVz += vz;
                    ffma2(aRxy, vv.x, sxy);       // (vx*sx, vy*sy)
                    aRz = fmaf(vz, sz, aRz);
                }
                float px, py, vxs, vys, rx, ry;
                upk2(aPxy, px, py);
                upk2(aVxy, vxs, vys);
                upk2(aRxy, rx, ry);
                sm[SSB + n * 36 + lane] = aS;
                sm[SP + (n * 3 + 0) * 36 + lane] = px;
                sm[SP + (n * 3 + 1) * 36 + lane] = py;
                sm[SP + (n * 3 + 2) * 36 + lane] = aPz;
                if (lane < 16) {
                    sm[SVB + (n * 3 + 0) * 20 + lane] = vxs;
                    sm[SVB + (n * 3 + 1) * 20 + lane] = vys;
                    sm[SVB + (n * 3 + 2) * 20 + lane] = aVz;
                    sm[SR + n * 20 + lane] = (rx + ry) + aRz;
                }
            }
        }
        cpa_wait<0>();
        __syncthreads();

        // ---- step A part 1 (64 threads, R=4 node blocking):
        //      a_v_i = C_VI*(p_i@W2 + Vbar_i@W3) -> registers ----
        u64 avv[12];   // [r*3+i]
        if (tid < 64) {
            const u64* w2u = (const u64*)(sW + 1024);
            const u64* w3u = (const u64*)(sW + 1536);
            #pragma unroll
            for (int i = 0; i < 3; ++i) {
                u64 ac0 = 0, ac1 = 0, ac2 = 0, ac3 = 0;
                #pragma unroll
                for (int u4 = 0; u4 < 8; ++u4) {
                    float4 p0 = ((const float4*)(sm + SP + ((4*dng+0)*3 + i)*36))[u4];
                    float4 p1 = ((const float4*)(sm + SP + ((4*dng+1)*3 + i)*36))[u4];
                    float4 p2 = ((const float4*)(sm + SP + ((4*dng+2)*3 + i)*36))[u4];
                    float4 p3 = ((const float4*)(sm + SP + ((4*dng+3)*3 + i)*36))[u4];
                    float e0[4] = {p0.x, p0.y, p0.z, p0.w};
                    float e1[4] = {p1.x, p1.y, p1.z, p1.w};
                    float e2[4] = {p2.x, p2.y, p2.z, p2.w};
                    float e3[4] = {p3.x, p3.y, p3.z, p3.w};
                    #pragma unroll
                    for (int j = 0; j < 4; ++j) {
                        u64 w = w2u[(u4 * 4 + j) * 8 + dq];
                        ffma2(ac0, splat2(e0[j]), w);
                        ffma2(ac1, splat2(e1[j]), w);
                        ffma2(ac2, splat2(e2[j]), w);
                        ffma2(ac3, splat2(e3[j]), w);
                    }
                }
                #pragma unroll
                for (int u4 = 0; u4 < 4; ++u4) {
                    float4 v0 = ((const float4*)(sm + SVB + ((4*dng+0)*3 + i)*20))[u4];
                    float4 v1 = ((const float4*)(sm + SVB + ((4*dng+1)*3 + i)*20))[u4];
                    float4 v2 = ((const float4*)(sm + SVB + ((4*dng+2)*3 + i)*20))[u4];
                    float4 v3 = ((const float4*)(sm + SVB + ((4*dng+3)*3 + i)*20))[u4];
                    float e0[4] = {v0.x, v0.y, v0.z, v0.w};
                    float e1[4] = {v1.x, v1.y, v1.z, v1.w};
                    float e2[4] = {v2.x, v2.y, v2.z, v2.w};
                    float e3[4] = {v3.x, v3.y, v3.z, v3.w};
                    #pragma unroll
                    for (int j = 0; j < 4; ++j) {
                        u64 w = w3u[(u4 * 4 + j) * 8 + dq];
                        ffma2(ac0, splat2(e0[j]), w);
                        ffma2(ac1, splat2(e1[j]), w);
                        ffma2(ac2, splat2(e2[j]), w);
                        ffma2(ac3, splat2(e3[j]), w);
                    }
                }
                avv[0 + i] = ac0; avv[3 + i] = ac1;
                avv[6 + i] = ac2; avv[9 + i] = ac3;
            }
        }
        __syncthreads();   // all sP/sVb reads done; aliased region writable

        // step A part 2: write a_v; a_s = C_S*(Sbar@W1 + INVS3*r@W4) -> SAS
        if (tid < 64) {
            #pragma unroll
            for (int r = 0; r < 4; ++r)
                #pragma unroll
                for (int i = 0; i < 3; ++i) {
                    float a0, a1;
                    upk2(avv[r * 3 + i], a0, a1);
                    *(float2*)(sm + SAV + ((4*dng+r)*3 + i)*20 + dq*2) =
                        make_float2(C_VI * a0, C_VI * a1);
                }

            u64 A01[4] = {0,0,0,0}, A23[4] = {0,0,0,0};
            {
                const ulonglong2* wf = (const ulonglong2*)sW;
                #pragma unroll
                for (int u4 = 0; u4 < 8; ++u4) {
                    float4 s0 = ((const float4*)(sm + SSB + (4*dng+0)*36))[u4];
                    float4 s1 = ((const float4*)(sm + SSB + (4*dng+1)*36))[u4];
                    float4 s2 = ((const float4*)(sm + SSB + (4*dng+2)*36))[u4];
                    float4 s3 = ((const float4*)(sm + SSB + (4*dng+3)*36))[u4];
                    float e0[4] = {s0.x, s0.y, s0.z, s0.w};
                    float e1[4] = {s1.x, s1.y, s1.z, s1.w};
                    float e2[4] = {s2.x, s2.y, s2.z, s2.w};
                    float e3[4] = {s3.x, s3.y, s3.z, s3.w};
                    #pragma unroll
                    for (int j = 0; j < 4; ++j) {
                        ulonglong2 w = wf[(u4 * 4 + j) * 8 + dq];
                        u64 t0 = splat2(e0[j]), t1 = splat2(e1[j]);
                        u64 t2 = splat2(e2[j]), t3 = splat2(e3[j]);
                        ffma2(A01[0], t0, w.x); ffma2(A23[0], t0, w.y);
                        ffma2(A01[1], t1, w.x); ffma2(A23[1], t1, w.y);
                        ffma2(A01[2], t2, w.x); ffma2(A23[2], t2, w.y);
                        ffma2(A01[3], t3, w.x); ffma2(A23[3], t3, w.y);
                    }
                }
                const ulonglong2* wf4 = (const ulonglong2*)(sW + 1792);
                #pragma unroll
                for (int u4 = 0; u4 < 4; ++u4) {
                    float4 r0 = ((const float4*)(sm + SR + (4*dng+0)*20))[u4];
                    float4 r1 = ((const float4*)(sm + SR + (4*dng+1)*20))[u4];
                    float4 r2 = ((const float4*)(sm + SR + (4*dng+2)*20))[u4];
                    float4 r3 = ((const float4*)(sm + SR + (4*dng+3)*20))[u4];
                    float e0[4] = {r0.x, r0.y, r0.z, r0.w};
                    float e1[4] = {r1.x, r1.y, r1.z, r1.w};
                    float e2[4] = {r2.x, r2.y, r2.z, r2.w};
                    float e3[4] = {r3.x, r3.y, r3.z, r3.w};
                    #pragma unroll
                    for (int j = 0; j < 4; ++j) {
                        ulonglong2 w = wf4[(u4 * 4 + j) * 8 + dq];
                        u64 t0 = splat2(e0[j] * INVS3), t1 = splat2(e1[j] * INVS3);
                        u64 t2 = splat2(e2[j] * INVS3), t3 = splat2(e3[j] * INVS3);
                        ffma2(A01[0], t0, w.x); ffma2(A23[0], t0, w.y);
                        ffma2(A01[1], t1, w.x); ffma2(A23[1], t1, w.y);
                        ffma2(A01[2], t2, w.x); ffma2(A23[2], t2, w.y);
                        ffma2(A01[3], t3, w.x); ffma2(A23[3], t3, w.y);
                    }
                }
            }
            #pragma unroll
            for (int r = 0; r < 4; ++r) {
                float a0, a1, a2, a3;
                upk2(A01[r], a0, a1); upk2(A23[r], a2, a3);
                float4 o;
                o.x = C_S * a0; o.y = C_S * a1;
                o.z = C_S * a2; o.w = C_S * a3;
                ((float4*)(sm + SAS + (4*dng+r)*36))[dq] = o;
            }
        }
        __syncthreads();

        // ---- step B (64 threads, R=4):
        //      s += relu((a_s@Ws)/sqrt32); v_i += relu((a_v_i@Wv)/4) ----
        if (tid < 64) {
            u64 A01[4] = {0,0,0,0}, A23[4] = {0,0,0,0};
            const ulonglong2* wf = (const ulonglong2*)(sW + 2304);
            #pragma unroll
            for (int u4 = 0; u4 < 8; ++u4) {
                float4 s0 = ((const float4*)(sm + SAS + (4*dng+0)*36))[u4];
                float4 s1 = ((const float4*)(sm + SAS + (4*dng+1)*36))[u4];
                float4 s2 = ((const float4*)(sm + SAS + (4*dng+2)*36))[u4];
                float4 s3 = ((const float4*)(sm + SAS + (4*dng+3)*36))[u4];
                float e0[4] = {s0.x, s0.y, s0.z, s0.w};
                float e1[4] = {s1.x, s1.y, s1.z, s1.w};
                float e2[4] = {s2.x, s2.y, s2.z, s2.w};
                float e3[4] = {s3.x, s3.y, s3.z, s3.w};
                #pragma unroll
                for (int j = 0; j < 4; ++j) {
                    ulonglong2 w = wf[(u4 * 4 + j) * 8 + dq];
                    u64 t0 = splat2(e0[j]), t1 = splat2(e1[j]);
                    u64 t2 = splat2(e2[j]), t3 = splat2(e3[j]);
                    ffma2(A01[0], t0, w.x); ffma2(A23[0], t0, w.y);
                    ffma2(A01[1], t1, w.x); ffma2(A23[1], t1, w.y);
                    ffma2(A01[2], t2, w.x); ffma2(A23[2], t2, w.y);
                    ffma2(A01[3], t3, w.x); ffma2(A23[3], t3, w.y);
                }
            }
            #pragma unroll
            for (int r = 0; r < 4; ++r) {
                float a0, a1, a2, a3;
                upk2(A01[r], a0, a1); upk2(A23[r], a2, a3);
                float4* sp = (float4*)(sm + SS + (4*dng+r)*36) + dq;
                float4 sv = *sp;
                sv.x += fmaxf(a0 * INV_SQ32, 0.f);
                sv.y += fmaxf(a1 * INV_SQ32, 0.f);
                sv.z += fmaxf(a2 * INV_SQ32, 0.f);
                sv.w += fmaxf(a3 * INV_SQ32, 0.f);
                *sp = sv;
            }

            const u64* wvu = (const u64*)(sW + 3328);
            float4* v4p = (float4*)(sm + SV4);
            #pragma unroll
            for (int i = 0; i < 3; ++i) {
                u64 ac[4] = {0,0,0,0};
                #pragma unroll
                for (int u4 = 0; u4 < 4; ++u4) {
                    float4 a0 = ((const float4*)(sm + SAV + ((4*dng+0)*3 + i)*20))[u4];
                    float4 a1 = ((const float4*)(sm + SAV + ((4*dng+1)*3 + i)*20))[u4];
                    float4 a2 = ((const float4*)(sm + SAV + ((4*dng+2)*3 + i)*20))[u4];
                    float4 a3 = ((const float4*)(sm + SAV + ((4*dng+3)*3 + i)*20))[u4];
                    float e0[4] = {a0.x, a0.y, a0.z, a0.w};
                    float e1[4] = {a1.x, a1.y, a1.z, a1.w};
                    float e2[4] = {a2.x, a2.y, a2.z, a2.w};
                    float e3[4] = {a3.x, a3.y, a3.z, a3.w};
                    #pragma unroll
                    for (int j = 0; j < 4; ++j) {
                        u64 w = wvu[(u4 * 4 + j) * 8 + dq];
                        ffma2(ac[0], splat2(e0[j]), w);
                        ffma2(ac[1], splat2(e1[j]), w);
                        ffma2(ac[2], splat2(e2[j]), w);
                        ffma2(ac[3], splat2(e3[j]), w);
                    }
                }
                #pragma unroll
                for (int r = 0; r < 4; ++r) {
                    float h0, h1;
                    upk2(ac[r], h0, h1);
                    int base = (4*dng + r) * 17 + dq * 2;
                    float4 vv = v4p[base];
                    ((float*)&vv)[i] += fmaxf(h0 * 0.25f, 0.f);
                    v4p[base] = vv;
                    vv = v4p[base + 1];
                    ((float*)&vv)[i] += fmaxf(h1 * 0.25f, 0.f);
                    v4p[base + 1] = vv;
                }
            }
        }
        __syncthreads();
    }

    // ---- pool ----
    if (tid < 80) {
        float acc = 0.f;
        if (tid < 32) {
            #pragma unroll
            for (int n = 0; n < 32; ++n) acc += sm[SS + n * 36 + tid];
        } else {
            int j = tid - 32;
            int w = j / 3, c = j - w * 3;
            #pragma unroll
            for (int n = 0; n < 32; ++n) acc += sm[SV4 + (n * 17 + w) * 4 + c];
        }
        g_hg[g * 80 + tid] = acc;
    }
}

// ---------------------------------------------------------------------------
// readout MLP: 16 graphs/CTA, single wave, cp.async double commit groups,
// H aliases the dead W1 buffer, packed f32x2 math. smem = 219648 B.
// ---------------------------------------------------------------------------
#define MW1  0        // 20480 (W1; H [16][256] aliases after phase 1)
#define MH   0
#define MW2  20480    // 32768
#define MA   53248    // 1280 [g][80]
#define MB1  54528    // 256
#define MB2  54784    // 128
#define SMEM_MLP (54912 * 4)

__global__ void __launch_bounds__(256, 1) k_mlp(
    const float* __restrict__ Wr1, const float* __restrict__ br1,
    const float* __restrict__ Wr2, const float* __restrict__ br2,
    float* __restrict__ out, int B)
{
    extern __shared__ float sm[];
    const int tid = threadIdx.x;
    const int g0  = blockIdx.x * 16;

    // group 1: W1 + A + biases
    {
        float4* w1d = (float4*)(sm + MW1);
        const float4* w1s = (const float4*)Wr1;
        #pragma unroll
        for (int i = 0; i < 20; ++i)
            cpa16(w1d + tid + 256 * i, w1s + tid + 256 * i);
        for (int idx = tid; idx < 320; idx += 256) {
            int gg = idx / 20, c = idx % 20;
            if (g0 + gg < B)
                cpa16((float4*)(sm + MA + gg * 80) + c,
                      (const float4*)(g_hg + (size_t)(g0 + gg) * 80) + c);
        }
        if (tid < 64)  cpa16((float4*)(sm + MB1) + tid, (const float4*)br1 + tid);
        if (tid < 32)  cpa16((float4*)(sm + MB2) + tid, (const float4*)br2 + tid);
        cpa_commit();
    }
    // group 2: W2
    {
        float4* w2d = (float4*)(sm + MW2);
        const float4* w2s = (const float4*)Wr2;
        #pragma unroll
        for (int i = 0; i < 32; ++i)
            cpa16(w2d + tid + 256 * i, w2s + tid + 256 * i);
        cpa_commit();
    }

    cpa_wait<1>();           // W1 + A ready (W2 still in flight)
    __syncthreads();

    // phase 1 -> registers: 4 graphs x 4 outputs per thread, packed
    const int gq = tid >> 6;
    const int oq = tid & 63;
    u64 c01[4], c23[4];
    #pragma unroll
    for (int gi = 0; gi < 4; ++gi) { c01[gi] = 0; c23[gi] = 0; }
    {
        const ulonglong2* w4p = (const ulonglong2*)(sm + MW1);
        #pragma unroll 4
        for (int k = 0; k < 80; ++k) {
            ulonglong2 w = w4p[k * 64 + oq];
            #pragma unroll
            for (int gi = 0; gi < 4; ++gi) {
                u64 a2 = splat2(sm[MA + (4 * gq + gi) * 80 + k]);
                ffma2(c01[gi], a2, w.x);
                ffma2(c23[gi], a2, w.y);
            }
        }
    }
    float4 b4 = ((const float4*)(sm + MB1))[oq];
    __syncthreads();         // all W1 reads done before H overwrites it

    {
        float4* h4p = (float4*)(sm + MH);
        #pragma unroll
        for (int gi = 0; gi < 4; ++gi) {
            float x0, x1, x2, x3;
            upk2(c01[gi], x0, x1); upk2(c23[gi], x2, x3);
            float4 hv;
            hv.x = fmaxf(x0 + b4.x, 0.f);
            hv.y = fmaxf(x1 + b4.y, 0.f);
            hv.z = fmaxf(x2 + b4.z, 0.f);
            hv.w = fmaxf(x3 + b4.w, 0.f);
            h4p[(4 * gq + gi) * 64 + oq] = hv;
        }
    }
    cpa_wait<0>();           // W2 ready
    __syncthreads();

    // phase 2: 2 graphs x 4 outputs per thread, packed
    {
        const int g2 = tid >> 5;
        const int o2 = tid & 31;
        u64 d0a = 0, d0b = 0, d1a = 0, d1b = 0;
        const ulonglong2* w4p = (const ulonglong2*)(sm + MW2);
        const float* h0 = sm + MH + (2 * g2) * 256;
        const float* h1 = sm + MH + (2 * g2 + 1) * 256;
        #pragma unroll 4
        for (int k = 0; k < 256; ++k) {
            u64 a0 = splat2(h0[k]);
            u64 a1 = splat2(h1[k]);
            ulonglong2 w = w4p[k * 32 + o2];
            ffma2(d0a, a0, w.x); ffma2(d0b, a0, w.y);
            ffma2(d1a, a1, w.x); ffma2(d1b, a1, w.y);
        }
        float4 bb = ((const float4*)(sm + MB2))[o2];
        int ga = g0 + 2 * g2, gb = ga + 1;
        float e0, e1, e2, e3;
        if (ga < B) {
            upk2(d0a, e0, e1); upk2(d0b, e2, e3);
            float4 o; o.x = e0 + bb.x; o.y = e1 + bb.y;
            o.z = e2 + bb.z; o.w = e3 + bb.w;
            ((float4*)(out + (size_t)ga * 128))[o2] = o;
        }
        if (gb < B) {
            upk2(d1a, e0, e1); upk2(d1b, e2, e3);
            float4 o; o.x = e0 + bb.x; o.y = e1 + bb.y;
            o.z = e2 + bb.z; o.w = e3 + bb.w;
            ((float4*)(out + (size_t)gb * 128))[o2] = o;
        }
    }
}

extern "C" void kernel_launch(void* const* d_in, const int* in_sizes, int n_in,
                              void* d_out, int out_size)
{
    int ie = -1;
    for (int i = 0; i < n_in; ++i)
        if (in_sizes[i] == 3200) { ie = i; break; }
    if (ie < 0) return;

    const float* pos = (const float*)d_in[0];
    int N = in_sizes[0] / 3;
    int B = N / 32;

    const float* emb  = (const float*)d_in[ie];
    const float* Ws2n = (const float*)d_in[ie + 1];
    const float* W1   = (const float*)d_in[ie + 2];
    const float* W2   = (const float*)d_in[ie + 3];
    const float* W3   = (const float*)d_in[ie + 4];
    const float* W4   = (const float*)d_in[ie + 5];
    const float* Ws   = (const float*)d_in[ie + 6];
    const float* Wv   = (const float*)d_in[ie + 7];
    const float* Wr1  = (const float*)d_in[ie + 8];
    const float* br1  = (const float*)d_in[ie + 9];
    const float* Wr2  = (const float*)d_in[ie + 10];
    const float* br2  = (const float*)d_in[ie + 11];

    const int* z = nullptr;
    for (int i = 1; i < n_in; ++i) {
        if (i >= ie && i <= ie + 11) continue;
        if (in_sizes[i] == N) { z = (const int*)d_in[i]; break; }  // z precedes batch
    }
    if (!z || B > MAXB || N > MAXN) return;

    cudaFuncSetAttribute((const void*)k_gnn,
                         cudaFuncAttributeMaxDynamicSharedMemorySize, SMEM_GNN);
    cudaFuncSetAttribute((const void*)k_mlp,
                         cudaFuncAttributeMaxDynamicSharedMemorySize, SMEM_MLP);

    k_gnn<<<B, 256, SMEM_GNN>>>(pos, z, emb, Ws2n, W1, W2, W3, W4, Ws, Wv);
    k_mlp<<<(B + 15) / 16, 256, SMEM_MLP>>>(Wr1, br1, Wr2, br2, (float*)d_out, B);
}

// round 14
// speedup vs baseline: 1.0273x; 1.0273x over previous
#include <cuda_runtime.h>

// ---------------------------------------------------------------------------
// EquivGNNEncoder on GB300, v10 = v8 + per-warp aliased scratch blocks.
// Dense phases are warp-local (warp w owns nodes 4w..4w+3 end to end), so
// sP / a_s / a_v live in per-warp 432-float blocks; the two mid-dense block
// barriers become __syncwarp. 2 block barriers per layer instead of 4.
// ---------------------------------------------------------------------------

#define MAXN (1 << 17)
#define MAXB 4096

typedef unsigned long long u64;

__device__ float g_hg[MAXB * 80];

__device__ __forceinline__ void cpa16(void* s, const void* g) {
    unsigned sa = (unsigned)__cvta_generic_to_shared(s);
    asm volatile("cp.async.cg.shared.global [%0], [%1], 16;\n" :: "r"(sa), "l"(g));
}
__device__ __forceinline__ void cpa_commit() {
    asm volatile("cp.async.commit_group;\n");
}
template<int N> __device__ __forceinline__ void cpa_wait() {
    asm volatile("cp.async.wait_group %0;\n" :: "n"(N) : "memory");
}

__device__ __forceinline__ u64 pk2(float lo, float hi) {
    u64 r; asm("mov.b64 %0, {%1, %2};" : "=l"(r) : "f"(lo), "f"(hi)); return r;
}
__device__ __forceinline__ u64 splat2(float v) { return pk2(v, v); }
__device__ __forceinline__ void upk2(u64 v, float& lo, float& hi) {
    asm("mov.b64 {%0, %1}, %2;" : "=f"(lo), "=f"(hi) : "l"(v));
}
__device__ __forceinline__ void ffma2(u64& d, u64 a, u64 b) {
    asm("fma.rn.f32x2 %0, %1, %2, %0;" : "+l"(d) : "l"(a), "l"(b));
}
__device__ __forceinline__ void fadd2(u64& d, u64 a) {
    asm("add.rn.f32x2 %0, %1, %0;" : "+l"(d) : "l"(a));
}

// smem float offsets (total 14272 floats = 57088 B -> 4 CTAs/SM):
#define SPOS 0        // pos float4 [32]        (128)
#define SS   128      // [n] stride 36          (1152)
#define SV4  1280     // float4 [n*17+w]        (2176)
#define SSB  3456     // S_bar [n] stride 36    (1152)
#define SR   4608     // r [n] stride 20        (640)
#define SVB  5248     // Vbar [(n*3+i)]*20      (1920)
#define SP   7168     // per-warp blocks of 432: p rows (nn*3+i)*36  (3456)
                      //   aliased after part1:  a_s nn*36 (0..144),
                      //                         a_v 144+(nn*3+i)*20 (144..384)
#define SW   10624    // 3584: [W1 0|W2 1024|W3 1536|W4 1792|Ws 2304|Wv 3328]
#define SADJ 14208
#define SZI  14240
#define SMEM_GNN (14272 * 4)

__global__ void __launch_bounds__(256, 4) k_gnn(
    const float* __restrict__ pos, const int* __restrict__ z,
    const float* __restrict__ emb, const float* __restrict__ Ws2n,
    const float* __restrict__ W1g, const float* __restrict__ W2g,
    const float* __restrict__ W3g, const float* __restrict__ W4g,
    const float* __restrict__ Wsg, const float* __restrict__ Wvg)
{
    extern __shared__ float sm[];
    float* sW = sm + SW;
    unsigned* sAdj = (unsigned*)(sm + SADJ);
    int*      sZi  = (int*)(sm + SZI);

    const int g    = blockIdx.x;
    const int tid  = threadIdx.x;
    const int n8   = tid >> 3;     // node (0..31)
    const int q8   = tid & 7;      // slice
    const int warp = tid >> 5;
    const int lane = tid & 31;
    const int nn   = (lane >> 3);  // local node within warp (0..3)
    const int wb   = warp * 432;   // per-warp scratch block base (in SP)

    const float SQRT3    = 1.7320508075688772f;
    const float INVS3    = 0.5773502691896258f;
    const float C_S      = 0.14433756729740643f;  // 1/sqrt(48)
    const float C_VI     = 0.14433756729740643f;
    const float INV_SQ32 = 0.17677669529663687f;
    const float R2       = 25.0f;

    // ---- stage Ws2n via cp.async; load statics ----
    cpa16((float4*)sW + tid, (const float4*)Ws2n + tid);
    cpa_commit();
    if (tid < 96) {
        int n = tid / 3, c = tid - n * 3;
        sm[SPOS + n * 4 + c] = pos[g * 96 + tid];
    }
    if (tid < 32) {
        sm[SPOS + tid * 4 + 3] = 0.f;
        sZi[tid] = z[g * 32 + tid];
    }
    __syncthreads();

    // ---- adjacency from pos (bit-identical to reference predicate) ----
    {
        const float4* pos4 = (const float4*)(sm + SPOS);
        float4 pm = pos4[lane];
        #pragma unroll
        for (int k = 0; k < 4; ++k) {
            int n = warp * 4 + k;
            float4 pn = pos4[n];
            float dx = __fsub_rn(pn.x, pm.x);
            float dy = __fsub_rn(pn.y, pm.y);
            float dz = __fsub_rn(pn.z, pm.z);
            float d2 = __fadd_rn(__fadd_rn(__fmul_rn(dx, dx), __fmul_rn(dy, dy)),
                                 __fmul_rn(dz, dz));
            unsigned msk = __ballot_sync(0xffffffffu, d2 <= R2 && d2 > 0.f);
            if (lane == 0) sAdj[n] = msk;
        }
    }

    // ---- emb gather, v = 0 ----
    {
        const float4* emb4 = (const float4*)emb;
        ((float4*)(sm + SSB + n8 * 36))[q8] = emb4[sZi[n8] * 8 + q8];
        float4 z4 = {0.f, 0.f, 0.f, 0.f};
        for (int i = tid; i < 544; i += 256) ((float4*)(sm + SV4))[i] = z4;
    }
    cpa_wait<0>();
    __syncthreads();

    // ---- initial s = (emb @ Ws2n)/sqrt(32), packed ----
    {
        u64 a01 = 0, a23 = 0;
        const float4* inf = (const float4*)(sm + SSB + n8 * 36);
        const ulonglong2* wf = (const ulonglong2*)sW;
        #pragma unroll
        for (int u4 = 0; u4 < 8; ++u4) {
            float4 s4 = inf[u4];
            float sv[4] = {s4.x, s4.y, s4.z, s4.w};
            #pragma unroll
            for (int j = 0; j < 4; ++j) {
                u64 sj = splat2(sv[j]);
                ulonglong2 w = wf[(u4 * 4 + j) * 8 + q8];
                ffma2(a01, sj, w.x);
                ffma2(a23, sj, w.y);
            }
        }
        float a0, a1, a2, a3;
        upk2(a01, a0, a1); upk2(a23, a2, a3);
        float4 o;
        o.x = a0 * INV_SQ32; o.y = a1 * INV_SQ32;
        o.z = a2 * INV_SQ32; o.w = a3 * INV_SQ32;
        ((float4*)(sm + SS + n8 * 36))[q8] = o;
    }
    __syncthreads();

    // ---- layers ----
    for (int l = 0; l < 3; ++l) {
        // stage layer weights (overlaps gather)
        {
            float4* wd = (float4*)sW;
            cpa16(wd + tid,        (const float4*)W1g + l * 256 + tid);        // W1
            cpa16(wd + 576 + tid,  (const float4*)Wsg + l * 256 + tid);        // Ws
            if (tid < 128)
                cpa16(wd + 256 + tid, (const float4*)W2g + l * 128 + tid);     // W2
            else
                cpa16(wd + 448 + (tid - 128),
                      (const float4*)W4g + l * 128 + (tid - 128));             // W4
            if (tid < 64)
                cpa16(wd + 384 + tid, (const float4*)W3g + l * 64 + tid);      // W3
            else if (tid < 128)
                cpa16(wd + 832 + (tid - 64),
                      (const float4*)Wvg + l * 64 + (tid - 64));               // Wv
            cpa_commit();
        }

        // ---- edge gather: warp w owns nodes 4w..4w+3; packed (x,y) pairs ----
        {
            int w2 = lane & 15;
            const float4* v4p = (const float4*)(sm + SV4);
            const float4* pos4 = (const float4*)(sm + SPOS);
            for (int k = 0; k < 4; ++k) {
                int n = warp * 4 + k;
                float4 pn = pos4[n];
                unsigned am = sAdj[n];
                float aS = 0.f, aPz = 0.f, aVz = 0.f, aRz = 0.f;
                u64 aPxy = 0, aVxy = 0, aRxy = 0;
                while (am) {
                    int m = __ffs(am) - 1;
                    am &= am - 1;
                    float4 pm = pos4[m];
                    float dx = pn.x - pm.x;
                    float dy = pn.y - pm.y;
                    float dz = pn.z - pm.z;
                    float iv = SQRT3 * rsqrtf(dx * dx + dy * dy + dz * dz);
                    float sx = dx * iv, sy = dy * iv, sz = dz * iv;
                    u64 sxy = pk2(sx, sy);
                    float su = sm[SS + m * 36 + lane];
                    aS += su;
                    ffma2(aPxy, splat2(su), sxy);
                    aPz = fmaf(su, sz, aPz);
                    ulonglong2 vv = *(const ulonglong2*)(v4p + m * 17 + w2);
                    fadd2(aVxy, vv.x);
                    float vz, vpad;
                    upk2(vv.y, vz, vpad);
                    aVz += vz;
                    ffma2(aRxy, vv.x, sxy);
                    aRz = fmaf(vz, sz, aRz);
                }
                float px, py, vxs, vys, rx, ry;
                upk2(aPxy, px, py);
                upk2(aVxy, vxs, vys);
                upk2(aRxy, rx, ry);
                sm[SSB + n * 36 + lane] = aS;
                sm[SP + wb + (k * 3 + 0) * 36 + lane] = px;
                sm[SP + wb + (k * 3 + 1) * 36 + lane] = py;
                sm[SP + wb + (k * 3 + 2) * 36 + lane] = aPz;
                if (lane < 16) {
                    sm[SVB + (n * 3 + 0) * 20 + lane] = vxs;
                    sm[SVB + (n * 3 + 1) * 20 + lane] = vys;
                    sm[SVB + (n * 3 + 2) * 20 + lane] = aVz;
                    sm[SR + n * 20 + lane] = (rx + ry) + aRz;
                }
            }
        }
        cpa_wait<0>();
        __syncthreads();   // weights visible + all gather writes done

        // ---- step A part 1: a_v_i = C_VI*(p_i@W2 + Vbar_i@W3) -> registers
        //      (reads only this warp's SP block + own-node SVB rows) ----
        float avv[3][2];
        {
            const u64* w2u = (const u64*)(sW + 1024);
            const u64* w3u = (const u64*)(sW + 1536);
            #pragma unroll
            for (int i = 0; i < 3; ++i) {
                u64 acc = 0;
                const float4* pf = (const float4*)(sm + SP + wb + (nn * 3 + i) * 36);
                #pragma unroll
                for (int u4 = 0; u4 < 8; ++u4) {
                    float4 p4 = pf[u4];
                    float pv[4] = {p4.x, p4.y, p4.z, p4.w};
                    #pragma unroll
                    for (int j = 0; j < 4; ++j)
                        ffma2(acc, splat2(pv[j]), w2u[(u4 * 4 + j) * 8 + q8]);
                }
                const float4* vbf = (const float4*)(sm + SVB + (n8 * 3 + i) * 20);
                #pragma unroll
                for (int u4 = 0; u4 < 4; ++u4) {
                    float4 v4 = vbf[u4];
                    float vval[4] = {v4.x, v4.y, v4.z, v4.w};
                    #pragma unroll
                    for (int j = 0; j < 4; ++j)
                        ffma2(acc, splat2(vval[j]), w3u[(u4 * 4 + j) * 8 + q8]);
                }
                float a0, a1;
                upk2(acc, a0, a1);
                avv[i][0] = C_VI * a0;
                avv[i][1] = C_VI * a1;
            }
        }
        __syncwarp();   // this warp's SP reads done; its aliased block writable

        // step A part 2: write a_v; a_s = C_S*(Sbar@W1 + INVS3*r@W4) -> a_s
        {
            #pragma unroll
            for (int i = 0; i < 3; ++i)
                *(float2*)(sm + SP + wb + 144 + (nn * 3 + i) * 20 + q8 * 2) =
                    make_float2(avv[i][0], avv[i][1]);

            u64 a01 = 0, a23 = 0;
            {
                const float4* inf = (const float4*)(sm + SSB + n8 * 36);
                const ulonglong2* wf = (const ulonglong2*)sW;
                #pragma unroll
                for (int u4 = 0; u4 < 8; ++u4) {
                    float4 s4 = inf[u4];
                    float sv[4] = {s4.x, s4.y, s4.z, s4.w};
                    #pragma unroll
                    for (int j = 0; j < 4; ++j) {
                        u64 sj = splat2(sv[j]);
                        ulonglong2 w = wf[(u4 * 4 + j) * 8 + q8];
                        ffma2(a01, sj, w.x);
                        ffma2(a23, sj, w.y);
                    }
                }
            }
            {
                const float4* inf = (const float4*)(sm + SR + n8 * 20);
                const ulonglong2* wf = (const ulonglong2*)(sW + 1792);
                #pragma unroll
                for (int u4 = 0; u4 < 4; ++u4) {
                    float4 r4 = inf[u4];
                    float rv[4] = {r4.x, r4.y, r4.z, r4.w};
                    #pragma unroll
                    for (int j = 0; j < 4; ++j) {
                        u64 rj = splat2(rv[j] * INVS3);
                        ulonglong2 w = wf[(u4 * 4 + j) * 8 + q8];
                        ffma2(a01, rj, w.x);
                        ffma2(a23, rj, w.y);
                    }
                }
            }
            float a0, a1, a2, a3;
            upk2(a01, a0, a1); upk2(a23, a2, a3);
            float4 o;
            o.x = C_S * a0; o.y = C_S * a1;
            o.z = C_S * a2; o.w = C_S * a3;
            ((float4*)(sm + SP + wb + nn * 36))[q8] = o;
        }
        __syncwarp();   // a_s/a_v of this warp's nodes complete

        // ---- step B: s += relu((a_s@Ws)/sqrt32); v_i += relu((a_v_i@Wv)/4) ----
        {
            u64 a01 = 0, a23 = 0;
            const float4* inf = (const float4*)(sm + SP + wb + nn * 36);
            const ulonglong2* wf = (const ulonglong2*)(sW + 2304);
            #pragma unroll
            for (int u4 = 0; u4 < 8; ++u4) {
                float4 a4 = inf[u4];
                float av_[4] = {a4.x, a4.y, a4.z, a4.w};
                #pragma unroll
                for (int j = 0; j < 4; ++j) {
                    u64 aj = splat2(av_[j]);
                    ulonglong2 w = wf[(u4 * 4 + j) * 8 + q8];
                    ffma2(a01, aj, w.x);
                    ffma2(a23, aj, w.y);
                }
            }
            float a0, a1, a2, a3;
            upk2(a01, a0, a1); upk2(a23, a2, a3);
            float4* sp = (float4*)(sm + SS + n8 * 36) + q8;
            float4 sv = *sp;
            sv.x += fmaxf(a0 * INV_SQ32, 0.f);
            sv.y += fmaxf(a1 * INV_SQ32, 0.f);
            sv.z += fmaxf(a2 * INV_SQ32, 0.f);
            sv.w += fmaxf(a3 * INV_SQ32, 0.f);
            *sp = sv;

            float hv[3][2];
            const u64* wvu = (const u64*)(sW + 3328);
            #pragma unroll
            for (int i = 0; i < 3; ++i) {
                u64 acc = 0;
                const float4* af = (const float4*)(sm + SP + wb + 144 + (nn * 3 + i) * 20);
                #pragma unroll
                for (int u4 = 0; u4 < 4; ++u4) {
                    float4 a4 = af[u4];
                    float av_[4] = {a4.x, a4.y, a4.z, a4.w};
                    #pragma unroll
                    for (int j = 0; j < 4; ++j)
                        ffma2(acc, splat2(av_[j]), wvu[(u4 * 4 + j) * 8 + q8]);
                }
                upk2(acc, hv[i][0], hv[i][1]);
            }
            float4* v4p = (float4*)(sm + SV4);
            #pragma unroll
            for (int k = 0; k < 2; ++k) {
                float4 vv = v4p[n8 * 17 + q8 * 2 + k];
                vv.x += fmaxf(hv[0][k] * 0.25f, 0.f);
                vv.y += fmaxf(hv[1][k] * 0.25f, 0.f);
                vv.z += fmaxf(hv[2][k] * 0.25f, 0.f);
                v4p[n8 * 17 + q8 * 2 + k] = vv;
            }
        }
        __syncthreads();   // layer exit: sS/sV4 consistent for next gather
    }

    // ---- pool ----
    if (tid < 80) {
        float acc = 0.f;
        if (tid < 32) {
            #pragma unroll
            for (int n = 0; n < 32; ++n) acc += sm[SS + n * 36 + tid];
        } else {
            int j = tid - 32;
            int w = j / 3, c = j - w * 3;
            #pragma unroll
            for (int n = 0; n < 32; ++n) acc += sm[SV4 + (n * 17 + w) * 4 + c];
        }
        g_hg[g * 80 + tid] = acc;
    }
}

// ---------------------------------------------------------------------------
// readout MLP: 16 graphs/CTA, single wave, cp.async double commit groups,
// H aliases the dead W1 buffer, packed f32x2 math. smem = 219648 B.
// ---------------------------------------------------------------------------
#define MW1  0        // 20480 (W1; H [16][256] aliases after phase 1)
#define MH   0
#define MW2  20480    // 32768
#define MA   53248    // 1280 [g][80]
#define MB1  54528    // 256
#define MB2  54784    // 128
#define SMEM_MLP (54912 * 4)

__global__ void __launch_bounds__(256, 1) k_mlp(
    const float* __restrict__ Wr1, const float* __restrict__ br1,
    const float* __restrict__ Wr2, const float* __restrict__ br2,
    float* __restrict__ out, int B)
{
    extern __shared__ float sm[];
    const int tid = threadIdx.x;
    const int g0  = blockIdx.x * 16;

    // group 1: W1 + A + biases
    {
        float4* w1d = (float4*)(sm + MW1);
        const float4* w1s = (const float4*)Wr1;
        #pragma unroll
        for (int i = 0; i < 20; ++i)
            cpa16(w1d + tid + 256 * i, w1s + tid + 256 * i);
        for (int idx = tid; idx < 320; idx += 256) {
            int gg = idx / 20, c = idx % 20;
            if (g0 + gg < B)
                cpa16((float4*)(sm + MA + gg * 80) + c,
                      (const float4*)(g_hg + (size_t)(g0 + gg) * 80) + c);
        }
        if (tid < 64)  cpa16((float4*)(sm + MB1) + tid, (const float4*)br1 + tid);
        if (tid < 32)  cpa16((float4*)(sm + MB2) + tid, (const float4*)br2 + tid);
        cpa_commit();
    }
    // group 2: W2
    {
        float4* w2d = (float4*)(sm + MW2);
        const float4* w2s = (const float4*)Wr2;
        #pragma unroll
        for (int i = 0; i < 32; ++i)
            cpa16(w2d + tid + 256 * i, w2s + tid + 256 * i);
        cpa_commit();
    }

    cpa_wait<1>();           // W1 + A ready (W2 still in flight)
    __syncthreads();

    // phase 1 -> registers: 4 graphs x 4 outputs per thread, packed
    const int gq = tid >> 6;
    const int oq = tid & 63;
    u64 c01[4], c23[4];
    #pragma unroll
    for (int gi = 0; gi < 4; ++gi) { c01[gi] = 0; c23[gi] = 0; }
    {
        const ulonglong2* w4p = (const ulonglong2*)(sm + MW1);
        #pragma unroll 4
        for (int k = 0; k < 80; ++k) {
            ulonglong2 w = w4p[k * 64 + oq];
            #pragma unroll
            for (int gi = 0; gi < 4; ++gi) {
                u64 a2 = splat2(sm[MA + (4 * gq + gi) * 80 + k]);
                ffma2(c01[gi], a2, w.x);
                ffma2(c23[gi], a2, w.y);
            }
        }
    }
    float4 b4 = ((const float4*)(sm + MB1))[oq];
    __syncthreads();         // all W1 reads done before H overwrites it

    {
        float4* h4p = (float4*)(sm + MH);
        #pragma unroll
        for (int gi = 0; gi < 4; ++gi) {
            float x0, x1, x2, x3;
            upk2(c01[gi], x0, x1); upk2(c23[gi], x2, x3);
            float4 hv;
            hv.x = fmaxf(x0 + b4.x, 0.f);
            hv.y = fmaxf(x1 + b4.y, 0.f);
            hv.z = fmaxf(x2 + b4.z, 0.f);
            hv.w = fmaxf(x3 + b4.w, 0.f);
            h4p[(4 * gq + gi) * 64 + oq] = hv;
        }
    }
    cpa_wait<0>();           // W2 ready
    __syncthreads();

    // phase 2: 2 graphs x 4 outputs per thread, packed
    {
        const int g2 = tid >> 5;
        const int o2 = tid & 31;
        u64 d0a = 0, d0b = 0, d1a = 0, d1b = 0;
        const ulonglong2* w4p = (const ulonglong2*)(sm + MW2);
        const float* h0 = sm + MH + (2 * g2) * 256;
        const float* h1 = sm + MH + (2 * g2 + 1) * 256;
        #pragma unroll 4
        for (int k = 0; k < 256; ++k) {
            u64 a0 = splat2(h0[k]);
            u64 a1 = splat2(h1[k]);
            ulonglong2 w = w4p[k * 32 + o2];
            ffma2(d0a, a0, w.x); ffma2(d0b, a0, w.y);
            ffma2(d1a, a1, w.x); ffma2(d1b, a1, w.y);
        }
        float4 bb = ((const float4*)(sm + MB2))[o2];
        int ga = g0 + 2 * g2, gb = ga + 1;
        float e0, e1, e2, e3;
        if (ga < B) {
            upk2(d0a, e0, e1); upk2(d0b, e2, e3);
            float4 o; o.x = e0 + bb.x; o.y = e1 + bb.y;
            o.z = e2 + bb.z; o.w = e3 + bb.w;
            ((float4*)(out + (size_t)ga * 128))[o2] = o;
        }
        if (gb < B) {
            upk2(d1a, e0, e1); upk2(d1b, e2, e3);
            float4 o; o.x = e0 + bb.x; o.y = e1 + bb.y;
            o.z = e2 + bb.z; o.w = e3 + bb.w;
            ((float4*)(out + (size_t)gb * 128))[o2] = o;
        }
    }
}

extern "C" void kernel_launch(void* const* d_in, const int* in_sizes, int n_in,
                              void* d_out, int out_size)
{
    int ie = -1;
    for (int i = 0; i < n_in; ++i)
        if (in_sizes[i] == 3200) { ie = i; break; }
    if (ie < 0) return;

    const float* pos = (const float*)d_in[0];
    int N = in_sizes[0] / 3;
    int B = N / 32;

    const float* emb  = (const float*)d_in[ie];
    const float* Ws2n = (const float*)d_in[ie + 1];
    const float* W1   = (const float*)d_in[ie + 2];
    const float* W2   = (const float*)d_in[ie + 3];
    const float* W3   = (const float*)d_in[ie + 4];
    const float* W4   = (const float*)d_in[ie + 5];
    const float* Ws   = (const float*)d_in[ie + 6];
    const float* Wv   = (const float*)d_in[ie + 7];
    const float* Wr1  = (const float*)d_in[ie + 8];
    const float* br1  = (const float*)d_in[ie + 9];
    const float* Wr2  = (const float*)d_in[ie + 10];
    const float* br2  = (const float*)d_in[ie + 11];

    const int* z = nullptr;
    for (int i = 1; i < n_in; ++i) {
        if (i >= ie && i <= ie + 11) continue;
        if (in_sizes[i] == N) { z = (const int*)d_in[i]; break; }  // z precedes batch
    }
    if (!z || B > MAXB || N > MAXN) return;

    cudaFuncSetAttribute((const void*)k_gnn,
                         cudaFuncAttributeMaxDynamicSharedMemorySize, SMEM_GNN);
    cudaFuncSetAttribute((const void*)k_mlp,
                         cudaFuncAttributeMaxDynamicSharedMemorySize, SMEM_MLP);

    k_gnn<<<B, 256, SMEM_GNN>>>(pos, z, emb, Ws2n, W1, W2, W3, W4, Ws, Wv);
    k_mlp<<<(B + 15) / 16, 256, SMEM_MLP>>>(Wr1, br1, Wr2, br2, (float*)d_out, B);
}